// round 11
// baseline (speedup 1.0000x reference)
#include <cuda_runtime.h>
#include <math.h>

// Problem shape (fixed by setup_inputs)
#define Bb   32
#define Hh   64
#define Ww   48
#define Cc   256
#define Dd   32
#define BG   256            // Bb * groups(8)
#define NPIX (Hh*Ww)        // 3072
#define LN_EPS 1e-3f

// Scratch (device globals — no allocation allowed)
__device__ float g_w2[BG*NPIX];    // per-pixel w2 = rs*(c·y - mu*csum) + cb
__device__ float g_weff[BG*9*Dd];  // x11-projected conv3x3 kernel
__device__ float g_beff[BG];       // dot(x11, conv3x3_b)

__device__ __forceinline__ float wsum(float v){
#pragma unroll
    for (int o = 16; o; o >>= 1) v += __shfl_xor_sync(0xffffffffu, v, o);
    return v;
}
__device__ __forceinline__ float wmax(float v){
#pragma unroll
    for (int o = 16; o; o >>= 1) v = fmaxf(v, __shfl_xor_sync(0xffffffffu, v, o));
    return v;
}

// Dynamic smem layout for fused kernel (floats):
#define F_ROW   0                  // s_row[64][32]
#define F_COLP  2048               // s_colp[4][48][32]
#define F_XH    8192               // s_xh[64][32]
#define F_XW    10240              // s_xw[48][32]
#define F_W1    11776              // smW[1024]
#define F_S9    12800              // smS[288]
#define F_SA    13088              // sA[16][32]
#define F_SB    13600              // sB[16]
#define F_X11   13616              // x11[32]
#define F_C     13648              // s_c[32]  (x21*gamma)
#define F_SC    13680              // s_scal[2] (csum, cb)
#define F_TOTAL 13684              // floats -> 54736 bytes

// ---------------------------------------------------------------------------
// Fused pass 1+2+3+4 (+ w2 field): one block (512 thr, 16 warps) per bg.
// ---------------------------------------------------------------------------
__global__ void __launch_bounds__(512, 1)
fused1234(const float* __restrict__ x,
          const float* __restrict__ w1x1,
          const float* __restrict__ b1,
          const float* __restrict__ w3,
          const float* __restrict__ b3,
          const float* __restrict__ gamma,
          const float* __restrict__ beta)
{
    extern __shared__ float sm[];
    float (*s_row)[Dd]       = (float(*)[Dd])(sm + F_ROW);
    float (*s_colp)[Ww][Dd]  = (float(*)[Ww][Dd])(sm + F_COLP);
    float (*s_xh)[Dd]        = (float(*)[Dd])(sm + F_XH);
    float (*s_xw)[Dd]        = (float(*)[Dd])(sm + F_XW);
    float *smW = sm + F_W1;
    float *smS = sm + F_S9;
    float (*sA)[Dd]          = (float(*)[Dd])(sm + F_SA);
    float *sB  = sm + F_SB;
    float *x11 = sm + F_X11;
    float *s_c = sm + F_C;
    float *s_scal = sm + F_SC;

    int bg = blockIdx.x;
    int b = bg >> 3, gi = bg & 7;
    int tid = threadIdx.x, lane = tid & 31, warp = tid >> 5;   // 16 warps
    int sg = lane >> 3, ch0 = (lane & 7) * 4;
    const float* xg = x + ((size_t)b*Hh)*Ww*Cc + gi*Dd + ch0;  // float4 base
    const float* xb = x + ((size_t)b*Hh)*Ww*Cc + gi*Dd + lane; // scalar base

    // stage conv1x1 weights (sync provided by the col-reduce rounds below)
    for (int i = tid; i < Dd*Dd; i += 512) smW[i] = w1x1[i];

    // ---- Phase A: warp owns rows warp*4..+3; register col partials ----
    float4 cacc[12];
#pragma unroll
    for (int s = 0; s < 12; ++s) cacc[s] = make_float4(0.f,0.f,0.f,0.f);
    {
        int r0 = warp * 4;
#pragma unroll
        for (int r = 0; r < 4; ++r) {
            int row = r0 + r;
            const float* rp = xg + (size_t)row*Ww*Cc;
            float4 racc = make_float4(0.f,0.f,0.f,0.f);
#pragma unroll
            for (int s = 0; s < 12; ++s) {
                float4 v = *(const float4*)(rp + (size_t)(s*4 + sg)*Cc);
                cacc[s].x += v.x; cacc[s].y += v.y; cacc[s].z += v.z; cacc[s].w += v.w;
                racc.x += v.x; racc.y += v.y; racc.z += v.z; racc.w += v.w;
            }
#pragma unroll
            for (int o = 8; o <= 16; o <<= 1) {
                racc.x += __shfl_xor_sync(0xffffffffu, racc.x, o);
                racc.y += __shfl_xor_sync(0xffffffffu, racc.y, o);
                racc.z += __shfl_xor_sync(0xffffffffu, racc.z, o);
                racc.w += __shfl_xor_sync(0xffffffffu, racc.w, o);
            }
            if (sg == 0) {
                racc.x *= (1.f/Ww); racc.y *= (1.f/Ww); racc.z *= (1.f/Ww); racc.w *= (1.f/Ww);
                *(float4*)&s_row[row][ch0] = racc;
            }
        }
    }
    // staged (atomic-free) cross-warp col reduction into 4 slots
    {
        int slot = warp & 3, grp = warp >> 2;
        if (grp == 0) {
#pragma unroll
            for (int s = 0; s < 12; ++s)
                *(float4*)&s_colp[slot][s*4 + sg][ch0] = cacc[s];
        }
        __syncthreads();
#pragma unroll
        for (int rd = 1; rd < 4; ++rd) {
            if (grp == rd) {
#pragma unroll
                for (int s = 0; s < 12; ++s) {
                    float4 t = *(float4*)&s_colp[slot][s*4 + sg][ch0];
                    t.x += cacc[s].x; t.y += cacc[s].y; t.z += cacc[s].z; t.w += cacc[s].w;
                    *(float4*)&s_colp[slot][s*4 + sg][ch0] = t;
                }
            }
            __syncthreads();
        }
    }
    // now col SUM (over 64 rows) of [w][ch] = sum over 4 slots

    // ---- Phase B (warps 1..15) / Phase C (warp 0), concurrent ----
    if (warp > 0) {
        float bias = b1[lane];
        for (int p = warp - 1; p < Hh + Ww; p += 15) {
            float v;
            if (p < Hh) v = s_row[p][lane];
            else {
                int w = p - Hh;
                v = (s_colp[0][w][lane] + s_colp[1][w][lane]
                   + s_colp[2][w][lane] + s_colp[3][w][lane]) * (1.0f/Hh);
            }
            float acc = bias;
#pragma unroll
            for (int i = 0; i < Dd; ++i) {
                float vi = __shfl_sync(0xffffffffu, v, i);
                acc += vi * smW[i*Dd + lane];
            }
            float s = 1.f/(1.f + expf(-acc));
            if (p < Hh) s_xh[p][lane] = s;
            else        s_xw[p-Hh][lane] = s;
        }
    } else {
        int i = lane;
        float T = 0.f;
#pragma unroll 8
        for (int h = 0; h < Hh; ++h) T += s_row[h][i];
        T *= (float)Ww;
        float R0 = s_row[0     ][i] * (float)Ww;
        float RL = s_row[Hh - 1][i] * (float)Ww;
        float C0 = s_colp[0][0][i] + s_colp[1][0][i] + s_colp[2][0][i] + s_colp[3][0][i];
        float CL = s_colp[0][Ww-1][i] + s_colp[1][Ww-1][i] + s_colp[2][Ww-1][i] + s_colp[3][Ww-1][i];
        float ctl = xb[0];
        float ctr = xb[(size_t)(Ww-1)*Cc];
        float cbl = xb[((size_t)(Hh-1)*Ww)*Cc];
        float cbr = xb[((size_t)(Hh-1)*Ww + (Ww-1))*Cc];
#pragma unroll
        for (int dy = -1; dy <= 1; ++dy) {
#pragma unroll
            for (int dx = -1; dx <= 1; ++dx) {
                float eR = (dy == -1) ? RL : (dy == 1) ? R0 : 0.f;
                float eC = (dx == -1) ? CL : (dx == 1) ? C0 : 0.f;
                float corner = 0.f;
                if (dy == -1 && dx == -1) corner = cbr;
                if (dy == -1 && dx ==  1) corner = cbl;
                if (dy ==  1 && dx == -1) corner = ctr;
                if (dy ==  1 && dx ==  1) corner = ctl;
                smS[((dy+1)*3 + (dx+1))*Dd + i] = T - eR - eC + corner;
            }
        }
        __syncwarp();
        int e = lane;
        float acc = 0.f;
        for (int k = 0; k < 9; ++k) {
#pragma unroll
            for (int ii = 0; ii < Dd; ++ii)
                acc += w3[(k*Dd + ii)*Dd + e] * smS[k*Dd + ii];
        }
        float m2 = acc * (1.f/NPIX) + b3[e];
        float mx = wmax(m2);
        float pz = expf(m2 - mx);
        float ps = wsum(pz);
        float x21 = pz/ps;
        float cv = x21 * gamma[e];
        s_c[e] = cv;
        float cs  = wsum(cv);
        float cbv = wsum(x21 * beta[e]);
        if (e == 0) { s_scal[0] = cs; s_scal[1] = cbv; }
    }
    __syncthreads();

    // ---- Phase D: LN-stat sweep + per-pixel w2 field ----
    {
        float4 cvq = *(const float4*)&s_c[ch0];
        float csum = s_scal[0], cb = s_scal[1];
        float4 accA = make_float4(0.f,0.f,0.f,0.f);
        float accB = 0.f;
        int p0 = warp * 192;
        float* w2out = g_w2 + bg*NPIX;
#pragma unroll 2
        for (int j = 0; j < 192; j += 4) {
            int p = p0 + j + sg;
            int h = p / Ww, w = p - h*Ww;
            float4 gx = *(const float4*)(xg + (size_t)p*Cc);
            float4 xh = *(const float4*)&s_xh[h][ch0];
            float4 xw = *(const float4*)&s_xw[w][ch0];
            float4 y;
            y.x = gx.x*xh.x*xw.x; y.y = gx.y*xh.y*xw.y;
            y.z = gx.z*xh.z*xw.z; y.w = gx.w*xh.w*xw.w;
            float a  = (y.x + y.y) + (y.z + y.w);
            float bq = (y.x*y.x + y.y*y.y) + (y.z*y.z + y.w*y.w);
            float cy = (cvq.x*y.x + cvq.y*y.y) + (cvq.z*y.z + cvq.w*y.w);
#pragma unroll
            for (int o = 4; o; o >>= 1) {
                a  += __shfl_xor_sync(0xffffffffu, a,  o);
                bq += __shfl_xor_sync(0xffffffffu, bq, o);
                cy += __shfl_xor_sync(0xffffffffu, cy, o);
            }
            float mu = a * (1.f/Dd);
            float var = bq * (1.f/Dd) - mu*mu;
            float rs = rsqrtf(var + LN_EPS);
            accA.x += rs*y.x; accA.y += rs*y.y; accA.z += rs*y.z; accA.w += rs*y.w;
            accB += rs*mu;
            float w2v = rs * (cy - mu*csum) + cb;
            if ((lane & 7) == 0) w2out[p] = w2v;
        }
#pragma unroll
        for (int o = 8; o <= 16; o <<= 1) {
            accA.x += __shfl_xor_sync(0xffffffffu, accA.x, o);
            accA.y += __shfl_xor_sync(0xffffffffu, accA.y, o);
            accA.z += __shfl_xor_sync(0xffffffffu, accA.z, o);
            accA.w += __shfl_xor_sync(0xffffffffu, accA.w, o);
        }
        if (sg == 0) *(float4*)&sA[warp][ch0] = accA;
        float bt = wsum(accB) * 0.125f;   // each pixel counted by 8 lanes
        if (lane == 0) sB[warp] = bt;
    }
    __syncthreads();

    // ---- Phase E: x11 softmax + beff (warp 0), then weff (288 threads) ----
    if (warp == 0) {
        int e = lane;
        float A = 0.f, Bs = 0.f;
#pragma unroll
        for (int k = 0; k < 16; ++k) { A += sA[k][e]; Bs += sB[k]; }
        float v = gamma[e] * (A - Bs) * (1.f/NPIX) + beta[e];
        float mx = wmax(v);
        float p = expf(v - mx);
        float ps = wsum(p);
        float xv = p/ps;
        x11[e] = xv;
        float be = wsum(xv * b3[e]);
        if (e == 0) g_beff[bg] = be;
    }
    __syncthreads();
    if (tid < 288) {
        int k = tid >> 5, i = tid & 31;
        const float4* wrow = (const float4*)(w3 + (size_t)(k*Dd + i)*Dd);
        float acc = 0.f;
#pragma unroll
        for (int e4 = 0; e4 < 8; ++e4) {
            float4 wv = __ldg(&wrow[e4]);
            acc += wv.x*x11[e4*4+0] + wv.y*x11[e4*4+1]
                 + wv.z*x11[e4*4+2] + wv.w*x11[e4*4+3];
        }
        g_weff[(bg*9 + k)*Dd + i] = acc;
    }
}

// ---------------------------------------------------------------------------
// Pass 5: double-buffered register column march.
// Block = 192 thr (6 warps) = 24 columns; marches a 16-row band.
// blockIdx: [bg (8b)] [band (2b)] [colhalf (1b)]  -> grid = BG*8
// Loads for row R+1 issue before row-dots consume row R (1 iter of cover).
// Incremental pointers; neighbor columns via immediate offsets.
// ---------------------------------------------------------------------------
__global__ void __launch_bounds__(192)
pass5(const float* __restrict__ x, float* __restrict__ out)
{
    int bg    = blockIdx.x >> 3;
    int r0    = ((blockIdx.x >> 1) & 3) * 16;
    int wbase = (blockIdx.x & 1) * 24;
    int b = bg >> 3, gi = bg & 7;
    int lane = threadIdx.x & 31, warp = threadIdx.x >> 5;   // 6 warps
    int sg = lane >> 3, ch0 = (lane & 7) * 4;
    int w = wbase + warp*4 + sg;                            // output column
    const int WC4 = Ww*Cc/4;                                // float4 row stride

    // per-thread constants
    float4 wk[9];
#pragma unroll
    for (int k = 0; k < 9; ++k) wk[k] = *(const float4*)&g_weff[(bg*9 + k)*Dd + ch0];
    float beff = g_beff[bg];
    bool has_m1 = (w > 0), has_p1 = (w < Ww-1);

    // running pointers
    const float4* rq = (const float4*)(x + ((size_t)b*Hh)*Ww*Cc + gi*Dd + ch0)
                       + (ptrdiff_t)(r0-1)*WC4 + w*(Cc/4);      // source row r0-1, center col
    float4* oq = (float4*)(out + ((size_t)b*Hh)*Ww*Cc + gi*Dd + ch0)
                 + (ptrdiff_t)r0*WC4 + w*(Cc/4);                // output row r0
    const float* w2r = g_w2 + bg*NPIX + w;                      // + row*Ww

    const float4 z = make_float4(0.f,0.f,0.f,0.f);
    float4 cm = z, c0 = z, cp = z;                               // current source row R
    if (r0 - 1 >= 0) {
        c0 = rq[0];
        if (has_m1) cm = rq[-(Cc/4)];
        if (has_p1) cp = rq[ (Cc/4)];
    }

    float4 a0 = z, a1 = z, pend = z;
    float4 gx_d1 = z, gx_d2 = z;
    float w2p = 0.f;

    for (int R = r0-1; R <= r0+17; ++R) {
        // 1) issue loads for source row R+1 (consumed next iteration)
        float4 nm = z, n0 = z, np = z;
        const float4* nq = rq + WC4;
        if ((unsigned)(R+1) < (unsigned)Hh && (R+1) <= r0+16) {
            n0 = nq[0];
            if (has_m1) nm = nq[-(Cc/4)];
            if (has_p1) np = nq[ (Cc/4)];
        }
        // 2) prefetch w2 for row R-1 (used at next iteration's emission)
        float w2_pf = 0.f;
        if (R-1 >= r0 && R-1 <= r0+15) w2_pf = w2r[(R-1)*Ww];

        // 3) emission for output row R-2 (depends only on previous iterations)
        if (R >= r0+2) {
            float conv = (pend.x + pend.y) + (pend.z + pend.w);
#pragma unroll
            for (int o2 = 4; o2; o2 >>= 1)
                conv += __shfl_xor_sync(0xffffffffu, conv, o2);
            float t = conv + beff + w2p;
            float gate = __fdividef(1.f, 1.f + __expf(-t));
            float4 o4;
            o4.x = gx_d2.x*gate; o4.y = gx_d2.y*gate;
            o4.z = gx_d2.z*gate; o4.w = gx_d2.w*gate;
            oq[0] = o4;
            oq += WC4;
        }

        // 4) row-dots for source row R (cur regs, loaded last iteration)
        float4 rd0, rd1, rd2;
        rd0.x = wk[0].x*cm.x + wk[1].x*c0.x + wk[2].x*cp.x;
        rd0.y = wk[0].y*cm.y + wk[1].y*c0.y + wk[2].y*cp.y;
        rd0.z = wk[0].z*cm.z + wk[1].z*c0.z + wk[2].z*cp.z;
        rd0.w = wk[0].w*cm.w + wk[1].w*c0.w + wk[2].w*cp.w;
        rd1.x = wk[3].x*cm.x + wk[4].x*c0.x + wk[5].x*cp.x;
        rd1.y = wk[3].y*cm.y + wk[4].y*c0.y + wk[5].y*cp.y;
        rd1.z = wk[3].z*cm.z + wk[4].z*c0.z + wk[5].z*cp.z;
        rd1.w = wk[3].w*cm.w + wk[4].w*c0.w + wk[5].w*cp.w;
        rd2.x = wk[6].x*cm.x + wk[7].x*c0.x + wk[8].x*cp.x;
        rd2.y = wk[6].y*cm.y + wk[7].y*c0.y + wk[8].y*cp.y;
        rd2.z = wk[6].z*cm.z + wk[7].z*c0.z + wk[8].z*cp.z;
        rd2.w = wk[6].w*cm.w + wk[7].w*c0.w + wk[8].w*cp.w;

        // 5) rotate pipeline state
        pend.x = a0.x + rd2.x; pend.y = a0.y + rd2.y;
        pend.z = a0.z + rd2.z; pend.w = a0.w + rd2.w;
        a0.x = a1.x + rd1.x; a0.y = a1.y + rd1.y;
        a0.z = a1.z + rd1.z; a0.w = a1.w + rd1.w;
        a1 = rd0;
        gx_d2 = gx_d1;
        gx_d1 = c0;
        w2p = w2_pf;
        cm = nm; c0 = n0; cp = np;
        rq = nq;
    }
}

// ---------------------------------------------------------------------------
extern "C" void kernel_launch(void* const* d_in, const int* in_sizes, int n_in,
                              void* d_out, int out_size)
{
    const float* x   = (const float*)d_in[0];
    const float* w1  = (const float*)d_in[1];
    const float* b1  = (const float*)d_in[2];
    const float* w3  = (const float*)d_in[3];
    const float* b3  = (const float*)d_in[4];
    const float* gm  = (const float*)d_in[5];
    const float* bt  = (const float*)d_in[6];
    float* out = (float*)d_out;

    static int configured = 0;
    if (!configured) {
        cudaFuncSetAttribute(fused1234, cudaFuncAttributeMaxDynamicSharedMemorySize,
                             F_TOTAL * 4);
        configured = 1;
    }

    fused1234<<<BG, 512, F_TOTAL*4>>>(x, w1, b1, w3, b3, gm, bt);
    pass5<<<BG*8, 192>>>(x, out);
}

// round 12
// speedup vs baseline: 1.1488x; 1.1488x over previous
#include <cuda_runtime.h>
#include <math.h>

// Problem shape (fixed by setup_inputs)
#define Bb   32
#define Hh   64
#define Ww   48
#define Cc   256
#define Dd   32
#define BG   256            // Bb * groups(8)
#define NPIX (Hh*Ww)        // 3072
#define LN_EPS 1e-3f

// Scratch (device globals — no allocation allowed)
__device__ float g_w2[BG*NPIX];    // per-pixel w2 = rs*(c·y - mu*csum) + cb
__device__ float g_weff[BG*9*Dd];  // x11-projected conv3x3 kernel
__device__ float g_beff[BG];       // dot(x11, conv3x3_b)

__device__ __forceinline__ float wsum(float v){
#pragma unroll
    for (int o = 16; o; o >>= 1) v += __shfl_xor_sync(0xffffffffu, v, o);
    return v;
}
__device__ __forceinline__ float wmax(float v){
#pragma unroll
    for (int o = 16; o; o >>= 1) v = fmaxf(v, __shfl_xor_sync(0xffffffffu, v, o));
    return v;
}

// Dynamic smem layout for fused kernel (floats):
#define F_ROW   0                  // s_row[64][32]
#define F_COLP  2048               // s_colp[4][48][32]
#define F_XH    8192               // s_xh[64][32]
#define F_XW    10240              // s_xw[48][32]
#define F_W1    11776              // smW[1024]
#define F_S9    12800              // smS[288]
#define F_SA    13088              // sA[16][32]
#define F_SB    13600              // sB[16]
#define F_X11   13616              // x11[32]
#define F_C     13648              // s_c[32]  (x21*gamma)
#define F_SC    13680              // s_scal[2] (csum, cb)
#define F_TOTAL 13684              // floats -> 54736 bytes

// ---------------------------------------------------------------------------
// Fused pass 1+2+3+4 (+ w2 field): one block (512 thr, 16 warps) per bg.
// ---------------------------------------------------------------------------
__global__ void __launch_bounds__(512, 1)
fused1234(const float* __restrict__ x,
          const float* __restrict__ w1x1,
          const float* __restrict__ b1,
          const float* __restrict__ w3,
          const float* __restrict__ b3,
          const float* __restrict__ gamma,
          const float* __restrict__ beta)
{
    extern __shared__ float sm[];
    float (*s_row)[Dd]       = (float(*)[Dd])(sm + F_ROW);
    float (*s_colp)[Ww][Dd]  = (float(*)[Ww][Dd])(sm + F_COLP);
    float (*s_xh)[Dd]        = (float(*)[Dd])(sm + F_XH);
    float (*s_xw)[Dd]        = (float(*)[Dd])(sm + F_XW);
    float *smW = sm + F_W1;
    float *smS = sm + F_S9;
    float (*sA)[Dd]          = (float(*)[Dd])(sm + F_SA);
    float *sB  = sm + F_SB;
    float *x11 = sm + F_X11;
    float *s_c = sm + F_C;
    float *s_scal = sm + F_SC;

    int bg = blockIdx.x;
    int b = bg >> 3, gi = bg & 7;
    int tid = threadIdx.x, lane = tid & 31, warp = tid >> 5;   // 16 warps
    int sg = lane >> 3, ch0 = (lane & 7) * 4;
    const float* xg = x + ((size_t)b*Hh)*Ww*Cc + gi*Dd + ch0;  // float4 base
    const float* xb = x + ((size_t)b*Hh)*Ww*Cc + gi*Dd + lane; // scalar base

    // stage conv1x1 weights (sync provided by the col-reduce rounds below)
    for (int i = tid; i < Dd*Dd; i += 512) smW[i] = w1x1[i];

    // ---- Phase A: warp owns rows warp*4..+3; register col partials ----
    float4 cacc[12];
#pragma unroll
    for (int s = 0; s < 12; ++s) cacc[s] = make_float4(0.f,0.f,0.f,0.f);
    {
        int r0 = warp * 4;
#pragma unroll
        for (int r = 0; r < 4; ++r) {
            int row = r0 + r;
            const float* rp = xg + (size_t)row*Ww*Cc;
            float4 racc = make_float4(0.f,0.f,0.f,0.f);
#pragma unroll
            for (int s = 0; s < 12; ++s) {
                float4 v = *(const float4*)(rp + (size_t)(s*4 + sg)*Cc);
                cacc[s].x += v.x; cacc[s].y += v.y; cacc[s].z += v.z; cacc[s].w += v.w;
                racc.x += v.x; racc.y += v.y; racc.z += v.z; racc.w += v.w;
            }
#pragma unroll
            for (int o = 8; o <= 16; o <<= 1) {
                racc.x += __shfl_xor_sync(0xffffffffu, racc.x, o);
                racc.y += __shfl_xor_sync(0xffffffffu, racc.y, o);
                racc.z += __shfl_xor_sync(0xffffffffu, racc.z, o);
                racc.w += __shfl_xor_sync(0xffffffffu, racc.w, o);
            }
            if (sg == 0) {
                racc.x *= (1.f/Ww); racc.y *= (1.f/Ww); racc.z *= (1.f/Ww); racc.w *= (1.f/Ww);
                *(float4*)&s_row[row][ch0] = racc;
            }
        }
    }
    // staged (atomic-free) cross-warp col reduction into 4 slots
    {
        int slot = warp & 3, grp = warp >> 2;
        if (grp == 0) {
#pragma unroll
            for (int s = 0; s < 12; ++s)
                *(float4*)&s_colp[slot][s*4 + sg][ch0] = cacc[s];
        }
        __syncthreads();
#pragma unroll
        for (int rd = 1; rd < 4; ++rd) {
            if (grp == rd) {
#pragma unroll
                for (int s = 0; s < 12; ++s) {
                    float4 t = *(float4*)&s_colp[slot][s*4 + sg][ch0];
                    t.x += cacc[s].x; t.y += cacc[s].y; t.z += cacc[s].z; t.w += cacc[s].w;
                    *(float4*)&s_colp[slot][s*4 + sg][ch0] = t;
                }
            }
            __syncthreads();
        }
    }
    // now col SUM (over 64 rows) of [w][ch] = sum over 4 slots

    // ---- Phase B (warps 1..15) / Phase C (warp 0), concurrent ----
    if (warp > 0) {
        float bias = b1[lane];
        for (int p = warp - 1; p < Hh + Ww; p += 15) {
            float v;
            if (p < Hh) v = s_row[p][lane];
            else {
                int w = p - Hh;
                v = (s_colp[0][w][lane] + s_colp[1][w][lane]
                   + s_colp[2][w][lane] + s_colp[3][w][lane]) * (1.0f/Hh);
            }
            float acc = bias;
#pragma unroll
            for (int i = 0; i < Dd; ++i) {
                float vi = __shfl_sync(0xffffffffu, v, i);
                acc += vi * smW[i*Dd + lane];
            }
            float s = 1.f/(1.f + expf(-acc));
            if (p < Hh) s_xh[p][lane] = s;
            else        s_xw[p-Hh][lane] = s;
        }
    } else {
        int i = lane;
        float T = 0.f;
#pragma unroll 8
        for (int h = 0; h < Hh; ++h) T += s_row[h][i];
        T *= (float)Ww;
        float R0 = s_row[0     ][i] * (float)Ww;
        float RL = s_row[Hh - 1][i] * (float)Ww;
        float C0 = s_colp[0][0][i] + s_colp[1][0][i] + s_colp[2][0][i] + s_colp[3][0][i];
        float CL = s_colp[0][Ww-1][i] + s_colp[1][Ww-1][i] + s_colp[2][Ww-1][i] + s_colp[3][Ww-1][i];
        float ctl = xb[0];
        float ctr = xb[(size_t)(Ww-1)*Cc];
        float cbl = xb[((size_t)(Hh-1)*Ww)*Cc];
        float cbr = xb[((size_t)(Hh-1)*Ww + (Ww-1))*Cc];
#pragma unroll
        for (int dy = -1; dy <= 1; ++dy) {
#pragma unroll
            for (int dx = -1; dx <= 1; ++dx) {
                float eR = (dy == -1) ? RL : (dy == 1) ? R0 : 0.f;
                float eC = (dx == -1) ? CL : (dx == 1) ? C0 : 0.f;
                float corner = 0.f;
                if (dy == -1 && dx == -1) corner = cbr;
                if (dy == -1 && dx ==  1) corner = cbl;
                if (dy ==  1 && dx == -1) corner = ctr;
                if (dy ==  1 && dx ==  1) corner = ctl;
                smS[((dy+1)*3 + (dx+1))*Dd + i] = T - eR - eC + corner;
            }
        }
        __syncwarp();
        int e = lane;
        float acc = 0.f;
        for (int k = 0; k < 9; ++k) {
#pragma unroll
            for (int ii = 0; ii < Dd; ++ii)
                acc += w3[(k*Dd + ii)*Dd + e] * smS[k*Dd + ii];
        }
        float m2 = acc * (1.f/NPIX) + b3[e];
        float mx = wmax(m2);
        float pz = expf(m2 - mx);
        float ps = wsum(pz);
        float x21 = pz/ps;
        float cv = x21 * gamma[e];
        s_c[e] = cv;
        float cs  = wsum(cv);
        float cbv = wsum(x21 * beta[e]);
        if (e == 0) { s_scal[0] = cs; s_scal[1] = cbv; }
    }
    __syncthreads();

    // ---- Phase D: LN-stat sweep + per-pixel w2 field ----
    {
        float4 cvq = *(const float4*)&s_c[ch0];
        float csum = s_scal[0], cb = s_scal[1];
        float4 accA = make_float4(0.f,0.f,0.f,0.f);
        float accB = 0.f;
        int p0 = warp * 192;
        float* w2out = g_w2 + bg*NPIX;
#pragma unroll 2
        for (int j = 0; j < 192; j += 4) {
            int p = p0 + j + sg;
            int h = p / Ww, w = p - h*Ww;
            float4 gx = *(const float4*)(xg + (size_t)p*Cc);
            float4 xh = *(const float4*)&s_xh[h][ch0];
            float4 xw = *(const float4*)&s_xw[w][ch0];
            float4 y;
            y.x = gx.x*xh.x*xw.x; y.y = gx.y*xh.y*xw.y;
            y.z = gx.z*xh.z*xw.z; y.w = gx.w*xh.w*xw.w;
            float a  = (y.x + y.y) + (y.z + y.w);
            float bq = (y.x*y.x + y.y*y.y) + (y.z*y.z + y.w*y.w);
            float cy = (cvq.x*y.x + cvq.y*y.y) + (cvq.z*y.z + cvq.w*y.w);
#pragma unroll
            for (int o = 4; o; o >>= 1) {
                a  += __shfl_xor_sync(0xffffffffu, a,  o);
                bq += __shfl_xor_sync(0xffffffffu, bq, o);
                cy += __shfl_xor_sync(0xffffffffu, cy, o);
            }
            float mu = a * (1.f/Dd);
            float var = bq * (1.f/Dd) - mu*mu;
            float rs = rsqrtf(var + LN_EPS);
            accA.x += rs*y.x; accA.y += rs*y.y; accA.z += rs*y.z; accA.w += rs*y.w;
            accB += rs*mu;
            float w2v = rs * (cy - mu*csum) + cb;
            if ((lane & 7) == 0) w2out[p] = w2v;
        }
#pragma unroll
        for (int o = 8; o <= 16; o <<= 1) {
            accA.x += __shfl_xor_sync(0xffffffffu, accA.x, o);
            accA.y += __shfl_xor_sync(0xffffffffu, accA.y, o);
            accA.z += __shfl_xor_sync(0xffffffffu, accA.z, o);
            accA.w += __shfl_xor_sync(0xffffffffu, accA.w, o);
        }
        if (sg == 0) *(float4*)&sA[warp][ch0] = accA;
        float bt = wsum(accB) * 0.125f;   // each pixel counted by 8 lanes
        if (lane == 0) sB[warp] = bt;
    }
    __syncthreads();

    // ---- Phase E: x11 softmax + beff (warp 0), then weff (288 threads) ----
    if (warp == 0) {
        int e = lane;
        float A = 0.f, Bs = 0.f;
#pragma unroll
        for (int k = 0; k < 16; ++k) { A += sA[k][e]; Bs += sB[k]; }
        float v = gamma[e] * (A - Bs) * (1.f/NPIX) + beta[e];
        float mx = wmax(v);
        float p = expf(v - mx);
        float ps = wsum(p);
        float xv = p/ps;
        x11[e] = xv;
        float be = wsum(xv * b3[e]);
        if (e == 0) g_beff[bg] = be;
    }
    __syncthreads();
    if (tid < 288) {
        int k = tid >> 5, i = tid & 31;
        const float4* wrow = (const float4*)(w3 + (size_t)(k*Dd + i)*Dd);
        float acc = 0.f;
#pragma unroll
        for (int e4 = 0; e4 < 8; ++e4) {
            float4 wv = __ldg(&wrow[e4]);
            acc += wv.x*x11[e4*4+0] + wv.y*x11[e4*4+1]
                 + wv.z*x11[e4*4+2] + wv.w*x11[e4*4+3];
        }
        g_weff[(bg*9 + k)*Dd + i] = acc;
    }
}

// ---------------------------------------------------------------------------
// Pass 5: single-buffer register column march, weff in SHARED memory.
// Block = 384 thr (12 warps) = full 48-column row; marches a 16-row band.
// blockIdx: [bg (8b)] [band (2b)]  -> grid = BG*4
// ---------------------------------------------------------------------------
__global__ void __launch_bounds__(384, 2)
pass5(const float* __restrict__ x, float* __restrict__ out)
{
    __shared__ __align__(16) float s_wk[9][Dd];   // 1152 B

    int bg = blockIdx.x >> 2;
    int r0 = (blockIdx.x & 3) * 16;
    int b = bg >> 3, gi = bg & 7;
    int tid = threadIdx.x;
    int lane = tid & 31, warp = tid >> 5;   // 12 warps
    int sg = lane >> 3, ch0 = (lane & 7) * 4;
    int w = warp*4 + sg;                    // output column 0..47
    const int WC4 = Ww*Cc/4;                // float4 row stride

    if (tid < 288) s_wk[tid >> 5][tid & 31] = g_weff[bg*9*Dd + tid];
    __syncthreads();

    float beff = g_beff[bg];
    bool has_m1 = (w > 0), has_p1 = (w < Ww-1);

    // running pointers
    const float4* rq = (const float4*)(x + ((size_t)b*Hh)*Ww*Cc + gi*Dd + ch0)
                       + (ptrdiff_t)(r0-1)*WC4 + w*(Cc/4);   // source row r0-1
    float4* oq = (float4*)(out + ((size_t)b*Hh)*Ww*Cc + gi*Dd + ch0)
                 + (ptrdiff_t)r0*WC4 + w*(Cc/4);             // output row r0
    const float* w2p_ptr = g_w2 + bg*NPIX + r0*Ww + w;       // w2 prefetch row r0

    const float4 z = make_float4(0.f,0.f,0.f,0.f);
    float4 a0 = z, a1 = z, pend = z;
    float4 gx_d1 = z, gx_d2 = z;
    float w2p = 0.f;

    for (int R = r0-1; R <= r0+17; ++R) {
        // 1) loads for source row R
        float4 vm = z, v0 = z, vp = z;
        if ((unsigned)R < (unsigned)Hh && R <= r0+16) {
            v0 = rq[0];
            if (has_m1) vm = rq[-(Cc/4)];
            if (has_p1) vp = rq[ (Cc/4)];
        }
        rq += WC4;
        // 2) prefetch w2 for row R-1 (used at next iteration's emission)
        float w2_pf = 0.f;
        if ((unsigned)(R-1-r0) < 16u) { w2_pf = *w2p_ptr; w2p_ptr += Ww; }

        // 3) emission for output row R-2 (depends on previous iterations only)
        if (R >= r0+2) {
            float conv = (pend.x + pend.y) + (pend.z + pend.w);
#pragma unroll
            for (int o2 = 4; o2; o2 >>= 1)
                conv += __shfl_xor_sync(0xffffffffu, conv, o2);
            float t = conv + beff + w2p;
            float gate = __fdividef(1.f, 1.f + __expf(-t));
            float4 o4;
            o4.x = gx_d2.x*gate; o4.y = gx_d2.y*gate;
            o4.z = gx_d2.z*gate; o4.w = gx_d2.w*gate;
            __stcs(oq, o4);
            oq += WC4;
        }

        // 4) row-dots for source row R; weights streamed from smem
        float4 k0 = *(const float4*)&s_wk[0][ch0];
        float4 k1 = *(const float4*)&s_wk[1][ch0];
        float4 k2 = *(const float4*)&s_wk[2][ch0];
        float4 rd0;
        rd0.x = k0.x*vm.x + k1.x*v0.x + k2.x*vp.x;
        rd0.y = k0.y*vm.y + k1.y*v0.y + k2.y*vp.y;
        rd0.z = k0.z*vm.z + k1.z*v0.z + k2.z*vp.z;
        rd0.w = k0.w*vm.w + k1.w*v0.w + k2.w*vp.w;
        k0 = *(const float4*)&s_wk[3][ch0];
        k1 = *(const float4*)&s_wk[4][ch0];
        k2 = *(const float4*)&s_wk[5][ch0];
        float4 rd1;
        rd1.x = k0.x*vm.x + k1.x*v0.x + k2.x*vp.x;
        rd1.y = k0.y*vm.y + k1.y*v0.y + k2.y*vp.y;
        rd1.z = k0.z*vm.z + k1.z*v0.z + k2.z*vp.z;
        rd1.w = k0.w*vm.w + k1.w*v0.w + k2.w*vp.w;
        k0 = *(const float4*)&s_wk[6][ch0];
        k1 = *(const float4*)&s_wk[7][ch0];
        k2 = *(const float4*)&s_wk[8][ch0];
        float4 rd2;
        rd2.x = k0.x*vm.x + k1.x*v0.x + k2.x*vp.x;
        rd2.y = k0.y*vm.y + k1.y*v0.y + k2.y*vp.y;
        rd2.z = k0.z*vm.z + k1.z*v0.z + k2.z*vp.z;
        rd2.w = k0.w*vm.w + k1.w*v0.w + k2.w*vp.w;

        // 5) rotate pipeline state
        pend.x = a0.x + rd2.x; pend.y = a0.y + rd2.y;
        pend.z = a0.z + rd2.z; pend.w = a0.w + rd2.w;
        a0.x = a1.x + rd1.x; a0.y = a1.y + rd1.y;
        a0.z = a1.z + rd1.z; a0.w = a1.w + rd1.w;
        a1 = rd0;
        gx_d2 = gx_d1;
        gx_d1 = v0;
        w2p = w2_pf;
    }
}

// ---------------------------------------------------------------------------
extern "C" void kernel_launch(void* const* d_in, const int* in_sizes, int n_in,
                              void* d_out, int out_size)
{
    const float* x   = (const float*)d_in[0];
    const float* w1  = (const float*)d_in[1];
    const float* b1  = (const float*)d_in[2];
    const float* w3  = (const float*)d_in[3];
    const float* b3  = (const float*)d_in[4];
    const float* gm  = (const float*)d_in[5];
    const float* bt  = (const float*)d_in[6];
    float* out = (float*)d_out;

    static int configured = 0;
    if (!configured) {
        cudaFuncSetAttribute(fused1234, cudaFuncAttributeMaxDynamicSharedMemorySize,
                             F_TOTAL * 4);
        configured = 1;
    }

    fused1234<<<BG, 512, F_TOTAL*4>>>(x, w1, b1, w3, b3, gm, bt);
    pass5<<<BG*4, 384>>>(x, out);
}